// round 1
// baseline (speedup 1.0000x reference)
#include <cuda_runtime.h>
#include <cstddef>

#define NB 8
#define NL 4096
#define ND 1024
#define NROWS (NB*NL)   // 32768

// ---- scratch (device globals; no allocation allowed) ----
__device__ float g_Q[(size_t)NROWS * ND];
__device__ float g_K[(size_t)NROWS * ND];
__device__ float g_V[(size_t)NROWS * ND];   // becomes U (=T@Vb) in place
__device__ float g_W[(size_t)NROWS * ND];   // W = T@Kb
__device__ float g_O[(size_t)NROWS * ND];
__device__ float g_beta[NROWS];
__device__ float g_A[(size_t)NB * 64 * 64 * 64];   // per-chunk A = (Q K^T)*tril

// =====================================================================
// SGEMM: C(MxN) = A(MxK) @ W(NxK)^T + bias(N)
// BM=BN=128, BK=16, 256 threads, 8x8 microtile
// =====================================================================
__global__ void __launch_bounds__(256, 2) sgemm_bias(
    const float* __restrict__ A, const float* __restrict__ Wm,
    const float* __restrict__ bias, float* __restrict__ C,
    int M, int N, int K)
{
    __shared__ float As[16][132];
    __shared__ float Bs[16][132];
    const int t  = threadIdx.x;
    const int m0 = blockIdx.y * 128;
    const int n0 = blockIdx.x * 128;
    const int tx = t & 15, ty = t >> 4;
    const int lr = t >> 2;          // 0..63
    const int lk = (t & 3) << 2;    // 0,4,8,12

    float acc[8][8];
#pragma unroll
    for (int i = 0; i < 8; i++)
#pragma unroll
        for (int j = 0; j < 8; j++) acc[i][j] = 0.f;

    for (int k0 = 0; k0 < K; k0 += 16) {
#pragma unroll
        for (int h = 0; h < 2; h++) {
            int m = lr + h * 64;
            float4 v = *(const float4*)&A[(size_t)(m0 + m) * K + k0 + lk];
            As[lk + 0][m] = v.x; As[lk + 1][m] = v.y;
            As[lk + 2][m] = v.z; As[lk + 3][m] = v.w;
            int nn = lr + h * 64;
            float4 w = *(const float4*)&Wm[(size_t)(n0 + nn) * K + k0 + lk];
            Bs[lk + 0][nn] = w.x; Bs[lk + 1][nn] = w.y;
            Bs[lk + 2][nn] = w.z; Bs[lk + 3][nn] = w.w;
        }
        __syncthreads();
#pragma unroll
        for (int kk = 0; kk < 16; kk++) {
            float a[8], b[8];
            *(float4*)(a)     = *(const float4*)&As[kk][ty * 8];
            *(float4*)(a + 4) = *(const float4*)&As[kk][ty * 8 + 4];
            *(float4*)(b)     = *(const float4*)&Bs[kk][tx * 8];
            *(float4*)(b + 4) = *(const float4*)&Bs[kk][tx * 8 + 4];
#pragma unroll
            for (int i = 0; i < 8; i++)
#pragma unroll
                for (int j = 0; j < 8; j++) acc[i][j] += a[i] * b[j];
        }
        __syncthreads();
    }
    float bv[8];
    *(float4*)(bv)     = *(const float4*)&bias[n0 + tx * 8];
    *(float4*)(bv + 4) = *(const float4*)&bias[n0 + tx * 8 + 4];
#pragma unroll
    for (int i = 0; i < 8; i++) {
        size_t off = (size_t)(m0 + ty * 8 + i) * N + n0 + tx * 8;
        float4 o1, o2;
        o1.x = acc[i][0] + bv[0]; o1.y = acc[i][1] + bv[1];
        o1.z = acc[i][2] + bv[2]; o1.w = acc[i][3] + bv[3];
        o2.x = acc[i][4] + bv[4]; o2.y = acc[i][5] + bv[5];
        o2.z = acc[i][6] + bv[6]; o2.w = acc[i][7] + bv[7];
        *(float4*)&C[off]     = o1;
        *(float4*)&C[off + 4] = o2;
    }
}

// =====================================================================
// beta[row] = 1 / (||K_row||^2 + 1e-6)   (one warp per row)
// =====================================================================
__global__ void __launch_bounds__(256) beta_kernel()
{
    int row  = blockIdx.x * 8 + (threadIdx.x >> 5);
    int lane = threadIdx.x & 31;
    const float* p = g_K + (size_t)row * ND;
    float s = 0.f;
#pragma unroll
    for (int i = 0; i < 8; i++) {
        float4 v = *(const float4*)&p[lane * 4 + i * 128];
        s += v.x * v.x + v.y * v.y + v.z * v.z + v.w * v.w;
    }
#pragma unroll
    for (int o = 16; o; o >>= 1) s += __shfl_xor_sync(0xffffffffu, s, o);
    if (lane == 0) g_beta[row] = 1.f / (s + 1e-6f);
}

// =====================================================================
// prep: per (batch, chunk) block
//   G = K K^T, AQ = Q K^T  -> T = -(beta_i*G)*tril_strict, A = AQ*tril_incl
//   forward-substitution inverse of (I - strict lower), T += I
//   W = T@Kb -> g_W ; U = T@Vb -> g_V (in place)
// =====================================================================
#define PPAD 35
__global__ void __launch_bounds__(256) prep_kernel()
{
    __shared__ float sA[64 * PPAD];
    __shared__ float sB[64 * PPAD];
    __shared__ float T_s[64 * 64];
    __shared__ float rowtmp[64];
    __shared__ float beta_s[64];

    const int t  = threadIdx.x;
    const int bc = blockIdx.x;
    const size_t row0 = (size_t)(bc >> 6) * NL + (size_t)(bc & 63) * 64;

    if (t < 64) beta_s[t] = g_beta[row0 + t];
    __syncthreads();

    const int i0  = (t >> 4) * 4;
    const int j0  = (t & 15) * 4;
    const int lkk = t & 31, ljr = t >> 5;

    float ga[4][4], qa[4][4];
#pragma unroll
    for (int a = 0; a < 4; a++)
#pragma unroll
        for (int b = 0; b < 4; b++) { ga[a][b] = 0.f; qa[a][b] = 0.f; }

    for (int k0 = 0; k0 < ND; k0 += 32) {
#pragma unroll
        for (int h = 0; h < 8; h++) {
            int j = ljr + h * 8;
            sA[j * PPAD + lkk] = g_K[(row0 + j) * ND + k0 + lkk];
            sB[j * PPAD + lkk] = g_Q[(row0 + j) * ND + k0 + lkk];
        }
        __syncthreads();
#pragma unroll
        for (int kk = 0; kk < 32; kk++) {
            float ki[4], kj[4], qi[4];
#pragma unroll
            for (int a = 0; a < 4; a++) {
                ki[a] = sA[(i0 + a) * PPAD + kk];
                qi[a] = sB[(i0 + a) * PPAD + kk];
                kj[a] = sA[(j0 + a) * PPAD + kk];
            }
#pragma unroll
            for (int a = 0; a < 4; a++)
#pragma unroll
                for (int b = 0; b < 4; b++) {
                    ga[a][b] += ki[a] * kj[b];
                    qa[a][b] += qi[a] * kj[b];
                }
        }
        __syncthreads();
    }

    float* Aout = g_A + (size_t)bc * 4096;
#pragma unroll
    for (int a = 0; a < 4; a++)
#pragma unroll
        for (int b = 0; b < 4; b++) {
            int i = i0 + a, j = j0 + b;
            T_s[i * 64 + j]  = (j < i) ? (-beta_s[i] * ga[a][b]) : 0.f;
            Aout[i * 64 + j] = (j <= i) ? qa[a][b] : 0.f;
        }
    __syncthreads();

    // forward substitution (matches the reference in-place update exactly)
    for (int i = 1; i < 64; i++) {
        if (t < i) rowtmp[t] = T_s[i * 64 + t];
        __syncthreads();
        if (t < i) {
            float s = 0.f;
            for (int j = t + 1; j < i; j++) s += rowtmp[j] * T_s[j * 64 + t];
            T_s[i * 64 + t] += s;
        }
        __syncthreads();
    }
    if (t < 64) T_s[t * 64 + t] += 1.f;
    __syncthreads();

    const int ip = (t >> 4) * 4;
    const int dp = (t & 15) * 2;
    for (int d0 = 0; d0 < ND; d0 += 32) {
#pragma unroll
        for (int h = 0; h < 8; h++) {
            int j = ljr + h * 8;
            float bj = beta_s[j];
            sA[j * PPAD + lkk] = g_K[(row0 + j) * ND + d0 + lkk] * bj;
            sB[j * PPAD + lkk] = g_V[(row0 + j) * ND + d0 + lkk] * bj;
        }
        __syncthreads();
        float wv[4][2], uv[4][2];
#pragma unroll
        for (int a = 0; a < 4; a++) { wv[a][0] = wv[a][1] = 0.f; uv[a][0] = uv[a][1] = 0.f; }
#pragma unroll
        for (int j = 0; j < 64; j++) {
            float kb0 = sA[j * PPAD + dp], kb1 = sA[j * PPAD + dp + 1];
            float vb0 = sB[j * PPAD + dp], vb1 = sB[j * PPAD + dp + 1];
#pragma unroll
            for (int a = 0; a < 4; a++) {
                float tv = T_s[(ip + a) * 64 + j];
                wv[a][0] += tv * kb0; wv[a][1] += tv * kb1;
                uv[a][0] += tv * vb0; uv[a][1] += tv * vb1;
            }
        }
#pragma unroll
        for (int a = 0; a < 4; a++) {
            size_t off = (row0 + ip + a) * ND + d0 + dp;
            *(float2*)&g_W[off] = make_float2(wv[a][0], wv[a][1]);
            *(float2*)&g_V[off] = make_float2(uv[a][0], uv[a][1]);
        }
        __syncthreads();
    }
}

// =====================================================================
// scan: one launch; grid (32 colblocks, 8 batches); S-slice (1024x32)
// resident in smem across all 64 chunks.
//   u = U0 - W@S ; o = A@u + Q@S ; S += K^T @ u
// =====================================================================
#define SPAD 40
#define SCAN_SMEM ((1024*SPAD + 64*32 + 64*64 + 2*32*66 + 64*34) * 4)

__global__ void __launch_bounds__(256, 1) scan_kernel()
{
    extern __shared__ float sm[];
    float* Ss  = sm;                    // [1024][SPAD]
    float* u_s = Ss  + 1024 * SPAD;     // [64][32]
    float* A_s = u_s + 64 * 32;         // [64][64]
    float* Wt  = A_s + 64 * 64;         // [32][66]  (kk-major, transposed)
    float* Qt  = Wt  + 32 * 66;
    float* Kt  = Qt  + 32 * 66;         // [64][34]  (row-major)

    const int t   = threadIdx.x;
    const int cb0 = blockIdx.x * 32;
    const int b   = blockIdx.y;

    for (int i = t; i < 1024 * SPAD; i += 256) Ss[i] = 0.f;

    const int r0  = (t >> 3) * 2;    // 2 rows
    const int c0  = (t & 7) * 4;     // 4 cols
    const int kp  = (t & 15) * 2;    // phase-d k pair
    const int cp  = (t >> 4) * 2;    // phase-d c pair
    const int lc4 = (t & 7) * 4;     // tile-load col
    const int lrb = t >> 3;          // tile-load row base (0..31)

    __syncthreads();

    for (int n = 0; n < 64; n++) {
        const size_t row0 = (size_t)b * NL + (size_t)n * 64;
        const float* Abase = g_A + ((size_t)b * 64 + n) * 4096;
#pragma unroll
        for (int i = 0; i < 16; i++) A_s[t + i * 256] = Abase[t + i * 256];

        float ua[2][4], qa[2][4];
#pragma unroll
        for (int rr = 0; rr < 2; rr++) {
            float4 v = *(const float4*)&g_V[(row0 + r0 + rr) * ND + cb0 + c0];
            ua[rr][0] = v.x; ua[rr][1] = v.y; ua[rr][2] = v.z; ua[rr][3] = v.w;
            qa[rr][0] = 0.f; qa[rr][1] = 0.f; qa[rr][2] = 0.f; qa[rr][3] = 0.f;
        }

        // ---- phase b: u = U0 - W@S ; qs = Q@S ----
        for (int kt = 0; kt < 32; kt++) {
            const int k0 = kt * 32;
#pragma unroll
            for (int h = 0; h < 2; h++) {
                int r = lrb + h * 32;
                float4 w = *(const float4*)&g_W[(row0 + r) * ND + k0 + lc4];
                Wt[(lc4 + 0) * 66 + r] = w.x; Wt[(lc4 + 1) * 66 + r] = w.y;
                Wt[(lc4 + 2) * 66 + r] = w.z; Wt[(lc4 + 3) * 66 + r] = w.w;
                float4 q = *(const float4*)&g_Q[(row0 + r) * ND + k0 + lc4];
                Qt[(lc4 + 0) * 66 + r] = q.x; Qt[(lc4 + 1) * 66 + r] = q.y;
                Qt[(lc4 + 2) * 66 + r] = q.z; Qt[(lc4 + 3) * 66 + r] = q.w;
            }
            __syncthreads();
#pragma unroll
            for (int kk = 0; kk < 32; kk++) {
                float4 s4 = *(const float4*)&Ss[(k0 + kk) * SPAD + c0];
                float2 w2 = *(const float2*)&Wt[kk * 66 + r0];
                float2 q2 = *(const float2*)&Qt[kk * 66 + r0];
                float sv[4] = {s4.x, s4.y, s4.z, s4.w};
#pragma unroll
                for (int x = 0; x < 4; x++) {
                    ua[0][x] -= w2.x * sv[x];
                    ua[1][x] -= w2.y * sv[x];
                    qa[0][x] += q2.x * sv[x];
                    qa[1][x] += q2.y * sv[x];
                }
            }
            __syncthreads();
        }

#pragma unroll
        for (int rr = 0; rr < 2; rr++)
            *(float4*)&u_s[(r0 + rr) * 32 + c0] =
                make_float4(ua[rr][0], ua[rr][1], ua[rr][2], ua[rr][3]);
        __syncthreads();

        // ---- phase c: o = A@u + qs ----
        float oa[2][4];
#pragma unroll
        for (int rr = 0; rr < 2; rr++)
#pragma unroll
            for (int x = 0; x < 4; x++) oa[rr][x] = qa[rr][x];
#pragma unroll
        for (int j = 0; j < 64; j++) {
            float a0 = A_s[r0 * 64 + j];
            float a1 = A_s[(r0 + 1) * 64 + j];
            float4 uu = *(const float4*)&u_s[j * 32 + c0];
            float uv[4] = {uu.x, uu.y, uu.z, uu.w};
#pragma unroll
            for (int x = 0; x < 4; x++) {
                oa[0][x] += a0 * uv[x];
                oa[1][x] += a1 * uv[x];
            }
        }
#pragma unroll
        for (int rr = 0; rr < 2; rr++)
            *(float4*)&g_O[(row0 + r0 + rr) * ND + cb0 + c0] =
                make_float4(oa[rr][0], oa[rr][1], oa[rr][2], oa[rr][3]);

        // ---- phase d: S += K^T @ u ----
        for (int kt = 0; kt < 32; kt++) {
            const int k0 = kt * 32;
#pragma unroll
            for (int h = 0; h < 2; h++) {
                int r = lrb + h * 32;
                float4 kv = *(const float4*)&g_K[(row0 + r) * ND + k0 + lc4];
                Kt[r * 34 + lc4 + 0] = kv.x; Kt[r * 34 + lc4 + 1] = kv.y;
                Kt[r * 34 + lc4 + 2] = kv.z; Kt[r * 34 + lc4 + 3] = kv.w;
            }
            __syncthreads();
            float a00 = 0.f, a01 = 0.f, a10 = 0.f, a11 = 0.f;
#pragma unroll
            for (int j = 0; j < 64; j++) {
                float2 kv = *(const float2*)&Kt[j * 34 + kp];
                float2 uv = *(const float2*)&u_s[j * 32 + cp];
                a00 += kv.x * uv.x; a01 += kv.x * uv.y;
                a10 += kv.y * uv.x; a11 += kv.y * uv.y;
            }
            float* sp = &Ss[(k0 + kp) * SPAD + cp];
            sp[0] += a00; sp[1] += a01;
            sp[SPAD] += a10; sp[SPAD + 1] += a11;
            __syncthreads();
        }
    }
}

// =====================================================================
extern "C" void kernel_launch(void* const* d_in, const int* in_sizes, int n_in,
                              void* d_out, int out_size)
{
    // inputs: X, [chunk], Wq_w, Wq_b, Wk_w, Wk_b, Wv_w, Wv_b, Wo_w, Wo_b
    int base = 1;
    if (n_in >= 10 && in_sizes[1] == 1) base = 2;
    const float* X    = (const float*)d_in[0];
    const float* Wq_w = (const float*)d_in[base + 0];
    const float* Wq_b = (const float*)d_in[base + 1];
    const float* Wk_w = (const float*)d_in[base + 2];
    const float* Wk_b = (const float*)d_in[base + 3];
    const float* Wv_w = (const float*)d_in[base + 4];
    const float* Wv_b = (const float*)d_in[base + 5];
    const float* Wo_w = (const float*)d_in[base + 6];
    const float* Wo_b = (const float*)d_in[base + 7];
    float* out = (float*)d_out;

    float *pQ, *pK, *pV, *pO;
    cudaGetSymbolAddress((void**)&pQ, g_Q);
    cudaGetSymbolAddress((void**)&pK, g_K);
    cudaGetSymbolAddress((void**)&pV, g_V);
    cudaGetSymbolAddress((void**)&pO, g_O);

    dim3 gg(ND / 128, NROWS / 128);
    sgemm_bias<<<gg, 256>>>(X, Wq_w, Wq_b, pQ, NROWS, ND, ND);
    sgemm_bias<<<gg, 256>>>(X, Wk_w, Wk_b, pK, NROWS, ND, ND);
    sgemm_bias<<<gg, 256>>>(X, Wv_w, Wv_b, pV, NROWS, ND, ND);
    beta_kernel<<<NROWS / 8, 256>>>();
    prep_kernel<<<NB * 64, 256>>>();
    cudaFuncSetAttribute(scan_kernel, cudaFuncAttributeMaxDynamicSharedMemorySize, SCAN_SMEM);
    scan_kernel<<<dim3(32, NB), 256, SCAN_SMEM>>>();
    sgemm_bias<<<gg, 256>>>(pO, Wo_w, Wo_b, out, NROWS, ND, ND);
}

// round 3
// speedup vs baseline: 1.2342x; 1.2342x over previous
#include <cuda_runtime.h>
#include <cstdint>
#include <cstddef>

#define NB 8
#define NL 4096
#define ND 1024
#define NROWS (NB*NL)   // 32768

// ---- scratch (device globals; no allocation allowed) ----
__device__ float g_Q[(size_t)NROWS * ND];
__device__ float g_K[(size_t)NROWS * ND];
__device__ float g_V[(size_t)NROWS * ND];   // becomes U (=T@Vb) in place
__device__ float g_W[(size_t)NROWS * ND];   // W = T@Kb
__device__ float g_O[(size_t)NROWS * ND];
__device__ float g_beta[NROWS];
__device__ float g_A[(size_t)NB * 64 * 64 * 64];   // per-chunk A = (Q K^T)*tril

__device__ __forceinline__ uint32_t f2tf32(float x) {
    uint32_t r;
    asm("cvt.rna.tf32.f32 %0, %1;" : "=r"(r) : "f"(x));
    return r;
}

// =====================================================================
// tf32 mma.sync GEMM: C(MxN) = A(MxK) @ W(NxK)^T + bias(N)
// CTA tile 128x128, BK=32, 256 thr (8 warps, 2x4), warp tile 64x32.
// smem pitch 36 floats -> conflict-free fragment LDS.
// =====================================================================
#define GPITCH 36
#define GASZ   (128 * GPITCH)          // floats per buffer per array
#define GSMEM  (4 * GASZ * 4)          // bytes: 2 arrays x 2 buffers

__global__ void __launch_bounds__(256, 1) gemm_mma(
    const float* __restrict__ A, const float* __restrict__ Wm,
    const float* __restrict__ bias, float* __restrict__ C,
    int M, int N, int K)
{
    extern __shared__ uint32_t smg[];
    // layout: A0 [0, GASZ), B0 [GASZ, 2GASZ), A1 [2GASZ, 3GASZ), B1 [3GASZ, 4GASZ)
    const int t    = threadIdx.x;
    const int wid  = t >> 5;
    const int lane = t & 31;
    const int wm   = wid & 1;        // 2 warp-rows (64 rows each)
    const int wn   = wid >> 1;       // 4 warp-cols (32 cols each)
    const int m0   = blockIdx.y * 128;
    const int n0   = blockIdx.x * 128;
    const int lr   = lane >> 2;      // 0..7
    const int lc   = lane & 3;       // 0..3

    const float* Ap = A  + (size_t)m0 * K;
    const float* Bp = Wm + (size_t)n0 * K;

    float acc[4][4][4];
#pragma unroll
    for (int i = 0; i < 4; i++)
#pragma unroll
        for (int j = 0; j < 4; j++)
#pragma unroll
            for (int x = 0; x < 4; x++) acc[i][j][x] = 0.f;

    // per-thread load mapping: idx = t + i*256 -> row idx>>3, col4 idx&7
    const int ldr = t >> 1;                 // NOT used; keep simple mapping below

    // ---- prologue: tile 0 -> buffer 0 ----
#pragma unroll
    for (int i = 0; i < 4; i++) {
        int idx = t + i * 256;
        int r = idx >> 3, c4 = idx & 7;
        float4 va = *(const float4*)(Ap + (size_t)r * K + c4 * 4);
        uint32_t* dst = &smg[r * GPITCH + c4 * 4];
        dst[0] = f2tf32(va.x); dst[1] = f2tf32(va.y);
        dst[2] = f2tf32(va.z); dst[3] = f2tf32(va.w);
        float4 vb = *(const float4*)(Bp + (size_t)r * K + c4 * 4);
        uint32_t* dstb = &smg[GASZ + r * GPITCH + c4 * 4];
        dstb[0] = f2tf32(vb.x); dstb[1] = f2tf32(vb.y);
        dstb[2] = f2tf32(vb.z); dstb[3] = f2tf32(vb.w);
    }
    __syncthreads();

    const int nkt = K >> 5;   // 32
    for (int kt = 0; kt < nkt; kt++) {
        const int cur = kt & 1;
        float4 ra[4], rb[4];
        if (kt + 1 < nkt) {
            const int ko = (kt + 1) * 32;
#pragma unroll
            for (int i = 0; i < 4; i++) {
                int idx = t + i * 256;
                int r = idx >> 3, c4 = idx & 7;
                ra[i] = *(const float4*)(Ap + (size_t)r * K + ko + c4 * 4);
                rb[i] = *(const float4*)(Bp + (size_t)r * K + ko + c4 * 4);
            }
        }

        const uint32_t* As = smg + cur * 2 * GASZ;
        const uint32_t* Bs = As + GASZ;
#pragma unroll
        for (int k8 = 0; k8 < 4; k8++) {
            const int kb = k8 * 8 + lc;
            uint32_t af[4][4], bf[4][2];
#pragma unroll
            for (int mt = 0; mt < 4; mt++) {
                int r = wm * 64 + mt * 16 + lr;
                af[mt][0] = As[r * GPITCH + kb];
                af[mt][1] = As[(r + 8) * GPITCH + kb];
                af[mt][2] = As[r * GPITCH + kb + 4];
                af[mt][3] = As[(r + 8) * GPITCH + kb + 4];
            }
#pragma unroll
            for (int nt = 0; nt < 4; nt++) {
                int n = wn * 32 + nt * 8 + lr;
                bf[nt][0] = Bs[n * GPITCH + kb];
                bf[nt][1] = Bs[n * GPITCH + kb + 4];
            }
#pragma unroll
            for (int mt = 0; mt < 4; mt++)
#pragma unroll
                for (int nt = 0; nt < 4; nt++) {
                    asm volatile(
                        "mma.sync.aligned.m16n8k8.row.col.f32.tf32.tf32.f32 "
                        "{%0,%1,%2,%3}, {%4,%5,%6,%7}, {%8,%9}, {%0,%1,%2,%3};"
                        : "+f"(acc[mt][nt][0]), "+f"(acc[mt][nt][1]),
                          "+f"(acc[mt][nt][2]), "+f"(acc[mt][nt][3])
                        : "r"(af[mt][0]), "r"(af[mt][1]), "r"(af[mt][2]), "r"(af[mt][3]),
                          "r"(bf[nt][0]), "r"(bf[nt][1]));
                }
        }

        if (kt + 1 < nkt) {
            uint32_t* dA = smg + (1 - cur) * 2 * GASZ;
            uint32_t* dB = dA + GASZ;
#pragma unroll
            for (int i = 0; i < 4; i++) {
                int idx = t + i * 256;
                int r = idx >> 3, c4 = idx & 7;
                uint32_t* da = &dA[r * GPITCH + c4 * 4];
                da[0] = f2tf32(ra[i].x); da[1] = f2tf32(ra[i].y);
                da[2] = f2tf32(ra[i].z); da[3] = f2tf32(ra[i].w);
                uint32_t* db = &dB[r * GPITCH + c4 * 4];
                db[0] = f2tf32(rb[i].x); db[1] = f2tf32(rb[i].y);
                db[2] = f2tf32(rb[i].z); db[3] = f2tf32(rb[i].w);
            }
        }
        __syncthreads();
    }

    // ---- epilogue: bias add + store ----
#pragma unroll
    for (int mt = 0; mt < 4; mt++) {
        int r = m0 + wm * 64 + mt * 16 + lr;
#pragma unroll
        for (int nt = 0; nt < 4; nt++) {
            int c = n0 + wn * 32 + nt * 8 + 2 * lc;
            float2 bv = *(const float2*)&bias[c];
            float2 o0, o1;
            o0.x = acc[mt][nt][0] + bv.x; o0.y = acc[mt][nt][1] + bv.y;
            o1.x = acc[mt][nt][2] + bv.x; o1.y = acc[mt][nt][3] + bv.y;
            *(float2*)&C[(size_t)r * N + c]       = o0;
            *(float2*)&C[(size_t)(r + 8) * N + c] = o1;
        }
    }
    (void)ldr;
}

// =====================================================================
// beta[row] = 1 / (||K_row||^2 + 1e-6)   (one warp per row)
// =====================================================================
__global__ void __launch_bounds__(256) beta_kernel()
{
    int row  = blockIdx.x * 8 + (threadIdx.x >> 5);
    int lane = threadIdx.x & 31;
    const float* p = g_K + (size_t)row * ND;
    float s = 0.f;
#pragma unroll
    for (int i = 0; i < 8; i++) {
        float4 v = *(const float4*)&p[lane * 4 + i * 128];
        s += v.x * v.x + v.y * v.y + v.z * v.z + v.w * v.w;
    }
#pragma unroll
    for (int o = 16; o; o >>= 1) s += __shfl_xor_sync(0xffffffffu, s, o);
    if (lane == 0) g_beta[row] = 1.f / (s + 1e-6f);
}

// =====================================================================
// prep: per (batch, chunk) block
// =====================================================================
#define PPAD 35
__global__ void __launch_bounds__(256) prep_kernel()
{
    __shared__ float sA[64 * PPAD];
    __shared__ float sB[64 * PPAD];
    __shared__ float T_s[64 * 64];
    __shared__ float rowtmp[64];
    __shared__ float beta_s[64];

    const int t  = threadIdx.x;
    const int bc = blockIdx.x;
    const size_t row0 = (size_t)(bc >> 6) * NL + (size_t)(bc & 63) * 64;

    if (t < 64) beta_s[t] = g_beta[row0 + t];
    __syncthreads();

    const int i0  = (t >> 4) * 4;
    const int j0  = (t & 15) * 4;
    const int lkk = t & 31, ljr = t >> 5;

    float ga[4][4], qa[4][4];
#pragma unroll
    for (int a = 0; a < 4; a++)
#pragma unroll
        for (int b = 0; b < 4; b++) { ga[a][b] = 0.f; qa[a][b] = 0.f; }

    for (int k0 = 0; k0 < ND; k0 += 32) {
#pragma unroll
        for (int h = 0; h < 8; h++) {
            int j = ljr + h * 8;
            sA[j * PPAD + lkk] = g_K[(row0 + j) * ND + k0 + lkk];
            sB[j * PPAD + lkk] = g_Q[(row0 + j) * ND + k0 + lkk];
        }
        __syncthreads();
#pragma unroll
        for (int kk = 0; kk < 32; kk++) {
            float ki[4], kj[4], qi[4];
#pragma unroll
            for (int a = 0; a < 4; a++) {
                ki[a] = sA[(i0 + a) * PPAD + kk];
                qi[a] = sB[(i0 + a) * PPAD + kk];
                kj[a] = sA[(j0 + a) * PPAD + kk];
            }
#pragma unroll
            for (int a = 0; a < 4; a++)
#pragma unroll
                for (int b = 0; b < 4; b++) {
                    ga[a][b] += ki[a] * kj[b];
                    qa[a][b] += qi[a] * kj[b];
                }
        }
        __syncthreads();
    }

    float* Aout = g_A + (size_t)bc * 4096;
#pragma unroll
    for (int a = 0; a < 4; a++)
#pragma unroll
        for (int b = 0; b < 4; b++) {
            int i = i0 + a, j = j0 + b;
            T_s[i * 64 + j]  = (j < i) ? (-beta_s[i] * ga[a][b]) : 0.f;
            Aout[i * 64 + j] = (j <= i) ? qa[a][b] : 0.f;
        }
    __syncthreads();

    for (int i = 1; i < 64; i++) {
        if (t < i) rowtmp[t] = T_s[i * 64 + t];
        __syncthreads();
        if (t < i) {
            float s = 0.f;
            for (int j = t + 1; j < i; j++) s += rowtmp[j] * T_s[j * 64 + t];
            T_s[i * 64 + t] += s;
        }
        __syncthreads();
    }
    if (t < 64) T_s[t * 64 + t] += 1.f;
    __syncthreads();

    const int ip = (t >> 4) * 4;
    const int dp = (t & 15) * 2;
    for (int d0 = 0; d0 < ND; d0 += 32) {
#pragma unroll
        for (int h = 0; h < 8; h++) {
            int j = ljr + h * 8;
            float bj = beta_s[j];
            sA[j * PPAD + lkk] = g_K[(row0 + j) * ND + d0 + lkk] * bj;
            sB[j * PPAD + lkk] = g_V[(row0 + j) * ND + d0 + lkk] * bj;
        }
        __syncthreads();
        float wv[4][2], uv[4][2];
#pragma unroll
        for (int a = 0; a < 4; a++) { wv[a][0] = wv[a][1] = 0.f; uv[a][0] = uv[a][1] = 0.f; }
#pragma unroll
        for (int j = 0; j < 64; j++) {
            float kb0 = sA[j * PPAD + dp], kb1 = sA[j * PPAD + dp + 1];
            float vb0 = sB[j * PPAD + dp], vb1 = sB[j * PPAD + dp + 1];
#pragma unroll
            for (int a = 0; a < 4; a++) {
                float tv = T_s[(ip + a) * 64 + j];
                wv[a][0] += tv * kb0; wv[a][1] += tv * kb1;
                uv[a][0] += tv * vb0; uv[a][1] += tv * vb1;
            }
        }
#pragma unroll
        for (int a = 0; a < 4; a++) {
            size_t off = (row0 + ip + a) * ND + d0 + dp;
            *(float2*)&g_W[off] = make_float2(wv[a][0], wv[a][1]);
            *(float2*)&g_V[off] = make_float2(uv[a][0], uv[a][1]);
        }
        __syncthreads();
    }
}

// =====================================================================
// scan: one launch; grid (32 colblocks, 8 batches); S-slice (1024x32)
// resident in smem across all 64 chunks.
// =====================================================================
#define SPAD 40
#define SCAN_SMEM ((1024*SPAD + 64*32 + 64*64 + 2*32*66 + 64*34) * 4)

__global__ void __launch_bounds__(256, 1) scan_kernel()
{
    extern __shared__ float smn[];
    float* Ss  = smn;                   // [1024][SPAD]
    float* u_s = Ss  + 1024 * SPAD;     // [64][32]
    float* A_s = u_s + 64 * 32;         // [64][64]
    float* Wt  = A_s + 64 * 64;         // [32][66]
    float* Qt  = Wt  + 32 * 66;
    float* Kt  = Qt  + 32 * 66;         // [64][34]

    const int t   = threadIdx.x;
    const int cb0 = blockIdx.x * 32;
    const int b   = blockIdx.y;

    for (int i = t; i < 1024 * SPAD; i += 256) Ss[i] = 0.f;

    const int r0  = (t >> 3) * 2;
    const int c0  = (t & 7) * 4;
    const int kp  = (t & 15) * 2;
    const int cp  = (t >> 4) * 2;
    const int lc4 = (t & 7) * 4;
    const int lrb = t >> 3;

    __syncthreads();

    for (int n = 0; n < 64; n++) {
        const size_t row0 = (size_t)b * NL + (size_t)n * 64;
        const float* Abase = g_A + ((size_t)b * 64 + n) * 4096;
#pragma unroll
        for (int i = 0; i < 16; i++) A_s[t + i * 256] = Abase[t + i * 256];

        float ua[2][4], qa[2][4];
#pragma unroll
        for (int rr = 0; rr < 2; rr++) {
            float4 v = *(const float4*)&g_V[(row0 + r0 + rr) * ND + cb0 + c0];
            ua[rr][0] = v.x; ua[rr][1] = v.y; ua[rr][2] = v.z; ua[rr][3] = v.w;
            qa[rr][0] = 0.f; qa[rr][1] = 0.f; qa[rr][2] = 0.f; qa[rr][3] = 0.f;
        }

        for (int kt = 0; kt < 32; kt++) {
            const int k0 = kt * 32;
#pragma unroll
            for (int h = 0; h < 2; h++) {
                int r = lrb + h * 32;
                float4 w = *(const float4*)&g_W[(row0 + r) * ND + k0 + lc4];
                Wt[(lc4 + 0) * 66 + r] = w.x; Wt[(lc4 + 1) * 66 + r] = w.y;
                Wt[(lc4 + 2) * 66 + r] = w.z; Wt[(lc4 + 3) * 66 + r] = w.w;
                float4 q = *(const float4*)&g_Q[(row0 + r) * ND + k0 + lc4];
                Qt[(lc4 + 0) * 66 + r] = q.x; Qt[(lc4 + 1) * 66 + r] = q.y;
                Qt[(lc4 + 2) * 66 + r] = q.z; Qt[(lc4 + 3) * 66 + r] = q.w;
            }
            __syncthreads();
#pragma unroll
            for (int kk = 0; kk < 32; kk++) {
                float4 s4 = *(const float4*)&Ss[(k0 + kk) * SPAD + c0];
                float2 w2 = *(const float2*)&Wt[kk * 66 + r0];
                float2 q2 = *(const float2*)&Qt[kk * 66 + r0];
                float sv[4] = {s4.x, s4.y, s4.z, s4.w};
#pragma unroll
                for (int x = 0; x < 4; x++) {
                    ua[0][x] -= w2.x * sv[x];
                    ua[1][x] -= w2.y * sv[x];
                    qa[0][x] += q2.x * sv[x];
                    qa[1][x] += q2.y * sv[x];
                }
            }
            __syncthreads();
        }

#pragma unroll
        for (int rr = 0; rr < 2; rr++)
            *(float4*)&u_s[(r0 + rr) * 32 + c0] =
                make_float4(ua[rr][0], ua[rr][1], ua[rr][2], ua[rr][3]);
        __syncthreads();

        float oa[2][4];
#pragma unroll
        for (int rr = 0; rr < 2; rr++)
#pragma unroll
            for (int x = 0; x < 4; x++) oa[rr][x] = qa[rr][x];
#pragma unroll
        for (int j = 0; j < 64; j++) {
            float a0 = A_s[r0 * 64 + j];
            float a1 = A_s[(r0 + 1) * 64 + j];
            float4 uu = *(const float4*)&u_s[j * 32 + c0];
            float uv[4] = {uu.x, uu.y, uu.z, uu.w};
#pragma unroll
            for (int x = 0; x < 4; x++) {
                oa[0][x] += a0 * uv[x];
                oa[1][x] += a1 * uv[x];
            }
        }
#pragma unroll
        for (int rr = 0; rr < 2; rr++)
            *(float4*)&g_O[(row0 + r0 + rr) * ND + cb0 + c0] =
                make_float4(oa[rr][0], oa[rr][1], oa[rr][2], oa[rr][3]);

        for (int kt = 0; kt < 32; kt++) {
            const int k0 = kt * 32;
#pragma unroll
            for (int h = 0; h < 2; h++) {
                int r = lrb + h * 32;
                float4 kv = *(const float4*)&g_K[(row0 + r) * ND + k0 + lc4];
                Kt[r * 34 + lc4 + 0] = kv.x; Kt[r * 34 + lc4 + 1] = kv.y;
                Kt[r * 34 + lc4 + 2] = kv.z; Kt[r * 34 + lc4 + 3] = kv.w;
            }
            __syncthreads();
            float a00 = 0.f, a01 = 0.f, a10 = 0.f, a11 = 0.f;
#pragma unroll
            for (int j = 0; j < 64; j++) {
                float2 kv = *(const float2*)&Kt[j * 34 + kp];
                float2 uv = *(const float2*)&u_s[j * 32 + cp];
                a00 += kv.x * uv.x; a01 += kv.x * uv.y;
                a10 += kv.y * uv.x; a11 += kv.y * uv.y;
            }
            float* sp = &Ss[(k0 + kp) * SPAD + cp];
            sp[0] += a00; sp[1] += a01;
            sp[SPAD] += a10; sp[SPAD + 1] += a11;
            __syncthreads();
        }
    }
}

// =====================================================================
extern "C" void kernel_launch(void* const* d_in, const int* in_sizes, int n_in,
                              void* d_out, int out_size)
{
    int base = 1;
    if (n_in >= 10 && in_sizes[1] == 1) base = 2;
    const float* X    = (const float*)d_in[0];
    const float* Wq_w = (const float*)d_in[base + 0];
    const float* Wq_b = (const float*)d_in[base + 1];
    const float* Wk_w = (const float*)d_in[base + 2];
    const float* Wk_b = (const float*)d_in[base + 3];
    const float* Wv_w = (const float*)d_in[base + 4];
    const float* Wv_b = (const float*)d_in[base + 5];
    const float* Wo_w = (const float*)d_in[base + 6];
    const float* Wo_b = (const float*)d_in[base + 7];
    float* out = (float*)d_out;

    float *pQ, *pK, *pV, *pO;
    cudaGetSymbolAddress((void**)&pQ, g_Q);
    cudaGetSymbolAddress((void**)&pK, g_K);
    cudaGetSymbolAddress((void**)&pV, g_V);
    cudaGetSymbolAddress((void**)&pO, g_O);

    cudaFuncSetAttribute(gemm_mma, cudaFuncAttributeMaxDynamicSharedMemorySize, GSMEM);
    dim3 gg(ND / 128, NROWS / 128);
    gemm_mma<<<gg, 256, GSMEM>>>(X, Wq_w, Wq_b, pQ, NROWS, ND, ND);
    gemm_mma<<<gg, 256, GSMEM>>>(X, Wk_w, Wk_b, pK, NROWS, ND, ND);
    gemm_mma<<<gg, 256, GSMEM>>>(X, Wv_w, Wv_b, pV, NROWS, ND, ND);
    beta_kernel<<<NROWS / 8, 256>>>();
    prep_kernel<<<NB * 64, 256>>>();
    cudaFuncSetAttribute(scan_kernel, cudaFuncAttributeMaxDynamicSharedMemorySize, SCAN_SMEM);
    scan_kernel<<<dim3(32, NB), 256, SCAN_SMEM>>>();
    gemm_mma<<<gg, 256, GSMEM>>>(pO, Wo_w, Wo_b, out, NROWS, ND, ND);
}